// round 13
// baseline (speedup 1.0000x reference)
#include <cuda_runtime.h>
#include <cuda_fp16.h>
#include <cstdint>

#define NV 200000
#define KK 27
#define CC 64
#define BM 128
#define NT 256
#define NWARP 8
#define STAGES 2
#define BN_EPS 1e-5f
#define PREP_GRID 512

#define A_BYTES (BM * 128)
#define B_BYTES (CC * 128)
#define STAGE_BYTES (A_BYTES + B_BYTES)            // 24576
#define SMEM_CONV (STAGES * STAGE_BYTES)           // 49152 -> 4 CTAs/SM

#define SW(o) ((o) ^ (((o) >> 3) & 0x70))

// ---------------- device scratch ----------------
__device__ alignas(256) __half g_y[(size_t)NV * CC];
__device__ alignas(256) __half g_t16[(size_t)NV * CC];
__device__ alignas(256) __half g_Wh[2][KK * CC * CC];
__device__ float g_sum[2][CC];
__device__ float g_sumsq[2][CC];
__device__ unsigned g_arrive;
__device__ int g_is64;

// ---------------- helpers ----------------
__device__ __forceinline__ uint32_t smem_u32(const void* p) {
    return (uint32_t)__cvta_generic_to_shared(p);
}
__device__ __forceinline__ void cp16(uint32_t dst, const void* src) {
    asm volatile("cp.async.cg.shared.global [%0], [%1], 16;\n" :: "r"(dst), "l"(src));
}
__device__ __forceinline__ int ld_idx(const void* nbr, bool is64, int gn, int k) {
    size_t pos = (size_t)gn * KK + k;
    return is64 ? (int)((const long long*)nbr)[pos] : ((const int*)nbr)[pos];
}

// ---------------- zero stats/counter + detect index dtype ----------------
__global__ void k_zero(const void* __restrict__ nbr) {
    int t = threadIdx.x;
    if (t < CC) {
        g_sum[0][t] = 0.f; g_sum[1][t] = 0.f;
        g_sumsq[0][t] = 0.f; g_sumsq[1][t] = 0.f;
    }
    if (t == 0) {
        g_arrive = 0u;
        const long long* p = (const long long*)nbr;
        int ok = 1;
        for (int i = 0; i < 64; ++i) {
            long long v = p[i];
            if (v < 0 || v >= NV) { ok = 0; break; }
        }
        g_is64 = ok;
    }
}

// ---------------- stats0 -> arrive -> wcvt (hidden in sync window) -> bnrelu0 ----------------
__global__ void k_prep(const float* __restrict__ x,
                       const float* __restrict__ W1,
                       const float* __restrict__ W2,
                       const float* __restrict__ gamma1,
                       const float* __restrict__ beta1) {
    // phase A: column stats over x
    __shared__ float sh[2][4][CC];
    {
        int ch = threadIdx.x & 63;
        int rg = threadIdx.x >> 6;
        float s = 0.f, s2 = 0.f;
        for (int row = blockIdx.x * 4 + rg; row < NV; row += gridDim.x * 4) {
            float v = x[(size_t)row * CC + ch];
            s += v; s2 += v * v;
        }
        sh[0][rg][ch] = s; sh[1][rg][ch] = s2;
        __syncthreads();
        if (rg == 0) {
            s  = sh[0][0][ch] + sh[0][1][ch] + sh[0][2][ch] + sh[0][3][ch];
            s2 = sh[1][0][ch] + sh[1][1][ch] + sh[1][2][ch] + sh[1][3][ch];
            atomicAdd(&g_sum[0][ch], s);
            atomicAdd(&g_sumsq[0][ch], s2);
        }
    }
    __threadfence();
    __syncthreads();
    if (threadIdx.x == 0) atomicAdd(&g_arrive, 1u);

    // weight conversion — runs while waiting for the last stats arrivals
    const int wtotal = KK * CC * CC;
    for (int i = blockIdx.x * blockDim.x + threadIdx.x; i < wtotal;
         i += gridDim.x * blockDim.x) {
        int k  = i >> 12;
        int ci = (i & 4095) >> 6;
        int co = i & 63;
        uint32_t off = (uint32_t)SW(ci * 128 + co * 2) >> 1;
        g_Wh[0][k * 4096 + off] = __float2half_rn(W1[i]);
        g_Wh[1][k * 4096 + off] = __float2half_rn(W2[i]);
    }

    // grid-wide sync (all PREP_GRID CTAs resident)
    if (threadIdx.x == 0) {
        while (atomicAdd(&g_arrive, 0u) < (unsigned)gridDim.x) {}
    }
    __syncthreads();

    // phase B: finalize + BN + ReLU + fp16 quantize into g_y
    __shared__ float s_scale[CC], s_shift[CC];
    if (threadIdx.x < CC) {
        int c = threadIdx.x;
        float mean = g_sum[0][c] / (float)NV;
        float var  = g_sumsq[0][c] / (float)NV - mean * mean;
        float s = gamma1[c] * rsqrtf(var + BN_EPS);
        s_scale[c] = s;
        s_shift[c] = beta1[c] - mean * s;
    }
    __syncthreads();
    const int total = NV * CC / 8;
    for (int i = blockIdx.x * blockDim.x + threadIdx.x; i < total;
         i += gridDim.x * blockDim.x) {
        int cb = (i & 7) << 3;
        float4 u0 = ((const float4*)x)[2 * i];
        float4 u1 = ((const float4*)x)[2 * i + 1];
        float f[8] = {u0.x, u0.y, u0.z, u0.w, u1.x, u1.y, u1.z, u1.w};
        #pragma unroll
        for (int j = 0; j < 8; ++j)
            f[j] = fmaxf(fmaf(f[j], s_scale[cb + j], s_shift[cb + j]), 0.f);
        uint4 o;
        *(__half2*)&o.x = __floats2half2_rn(f[0], f[1]);
        *(__half2*)&o.y = __floats2half2_rn(f[2], f[3]);
        *(__half2*)&o.z = __floats2half2_rn(f[4], f[5]);
        *(__half2*)&o.w = __floats2half2_rn(f[6], f[7]);
        ((uint4*)g_y)[i] = o;
    }
}

// ---------------- bnrelu stage1: loop-free, one uint4 per thread ----------------
__global__ void k_bnrelu1(const float* __restrict__ gamma,
                          const float* __restrict__ beta) {
    __shared__ float s_scale[CC], s_shift[CC];
    if (threadIdx.x < CC) {
        int c = threadIdx.x;
        float mean = g_sum[1][c] / (float)NV;
        float var  = g_sumsq[1][c] / (float)NV - mean * mean;
        float s = gamma[c] * rsqrtf(var + BN_EPS);
        s_scale[c] = s;
        s_shift[c] = beta[c] - mean * s;
    }
    __syncthreads();
    const int i = blockIdx.x * blockDim.x + threadIdx.x;
    if (i >= NV * CC / 8) return;
    int cb = (i & 7) << 3;
    uint4 u = ((const uint4*)g_t16)[i];
    float2 p0 = __half22float2(*(__half2*)&u.x);
    float2 p1 = __half22float2(*(__half2*)&u.y);
    float2 p2 = __half22float2(*(__half2*)&u.z);
    float2 p3 = __half22float2(*(__half2*)&u.w);
    float f[8] = {p0.x, p0.y, p1.x, p1.y, p2.x, p2.y, p3.x, p3.y};
    #pragma unroll
    for (int j = 0; j < 8; ++j)
        f[j] = fmaxf(fmaf(f[j], s_scale[cb + j], s_shift[cb + j]), 0.f);
    uint4 o;
    *(__half2*)&o.x = __floats2half2_rn(f[0], f[1]);
    *(__half2*)&o.y = __floats2half2_rn(f[2], f[3]);
    *(__half2*)&o.z = __floats2half2_rn(f[4], f[5]);
    *(__half2*)&o.w = __floats2half2_rn(f[6], f[7]);
    ((uint4*)g_y)[i] = o;
}

// ---------------- gather-GEMM conv: BM=128, 8 warps (4m x 2n, m32n32), occ 4 ----------------
__global__ void __launch_bounds__(NT, 4)
k_conv(const void* __restrict__ nbr, int which,
       const float* __restrict__ residual, float* __restrict__ dout)
{
    extern __shared__ char smem[];
    const uint32_t sb = smem_u32(smem);
    const __half* __restrict__ Wh = g_Wh[which];

    const int tid = threadIdx.x;
    const int warp = tid >> 5, lane = tid & 31;
    const int wm = warp >> 1, wn = warp & 1;
    const int m0 = blockIdx.x * BM;
    const bool is64 = (g_is64 != 0);

    float acc[2][4][4];
    #pragma unroll
    for (int a = 0; a < 2; ++a)
        #pragma unroll
        for (int b = 0; b < 4; ++b)
            #pragma unroll
            for (int c = 0; c < 4; ++c) acc[a][b][c] = 0.f;

    const int r  = tid >> 1;
    const int hs = tid & 1;
    const int gn = (m0 + r < NV) ? (m0 + r) : 0;

    auto fill = [&](int st, int gi, int k) {
        const __half* srcA = g_y + (size_t)gi * CC + hs * 32;
        uint32_t abase = sb + st * STAGE_BYTES;
        #pragma unroll
        for (int j = 0; j < 4; ++j) {
            uint32_t boff = (uint32_t)(r * 128 + (hs * 4 + j) * 16);
            cp16(abase + SW(boff), srcA + j * 8);
        }
        const __half* srcB = Wh + k * 4096;
        uint32_t bbase = abase + A_BYTES;
        cp16(bbase + tid * 16,        srcB + tid * 8);
        cp16(bbase + (tid + NT) * 16, srcB + (tid + NT) * 8);
    };

    {
        int i0 = ld_idx(nbr, is64, gn, 0);
        int i1 = ld_idx(nbr, is64, gn, 1);
        fill(0, i0, 0);
        asm volatile("cp.async.commit_group;\n");
        fill(1, i1, 1);
        asm volatile("cp.async.commit_group;\n");
    }
    int gi_next = ld_idx(nbr, is64, gn, 2);

    for (int k = 0; k < KK; ++k) {
        const int st = k & 1;
        if (k + 1 < KK)
            asm volatile("cp.async.wait_group 1;\n");
        else
            asm volatile("cp.async.wait_group 0;\n");
        __syncthreads();

        const uint32_t abase = sb + st * STAGE_BYTES;
        const uint32_t bbase = abase + A_BYTES;

        #pragma unroll
        for (int ks = 0; ks < 4; ++ks) {
            const int k0 = ks * 16;
            uint32_t a0[4], a1[4], b0[4], b1[4];
            {
                int row = wm * 32 + (lane & 15);
                int col = k0 + (lane >> 4) * 8;
                uint32_t ad = abase + SW((uint32_t)(row * 128 + col * 2));
                asm volatile("ldmatrix.sync.aligned.m8n8.x4.shared.b16 {%0,%1,%2,%3}, [%4];"
                             : "=r"(a0[0]), "=r"(a0[1]), "=r"(a0[2]), "=r"(a0[3]) : "r"(ad));
                ad = abase + SW((uint32_t)((row + 16) * 128 + col * 2));
                asm volatile("ldmatrix.sync.aligned.m8n8.x4.shared.b16 {%0,%1,%2,%3}, [%4];"
                             : "=r"(a1[0]), "=r"(a1[1]), "=r"(a1[2]), "=r"(a1[3]) : "r"(ad));
            }
            {
                int krow = k0 + ((lane >> 3) & 1) * 8 + (lane & 7);
                int coll = wn * 32 + (lane >> 4) * 8;
                uint32_t ad = bbase + SW((uint32_t)(krow * 128 + coll * 2));
                asm volatile("ldmatrix.sync.aligned.m8n8.x4.trans.shared.b16 {%0,%1,%2,%3}, [%4];"
                             : "=r"(b0[0]), "=r"(b0[1]), "=r"(b0[2]), "=r"(b0[3]) : "r"(ad));
                ad = bbase + SW((uint32_t)(krow * 128 + (coll + 16) * 2));
                asm volatile("ldmatrix.sync.aligned.m8n8.x4.trans.shared.b16 {%0,%1,%2,%3}, [%4];"
                             : "=r"(b1[0]), "=r"(b1[1]), "=r"(b1[2]), "=r"(b1[3]) : "r"(ad));
            }
            #pragma unroll
            for (int mt = 0; mt < 2; ++mt) {
                const uint32_t* A = mt ? a1 : a0;
                #pragma unroll
                for (int nt = 0; nt < 4; ++nt) {
                    const uint32_t* B = (nt < 2) ? b0 : b1;
                    uint32_t bb0 = B[(nt & 1) * 2], bb1 = B[(nt & 1) * 2 + 1];
                    float* C = acc[mt][nt];
                    asm volatile(
                        "mma.sync.aligned.m16n8k16.row.col.f32.f16.f16.f32 "
                        "{%0,%1,%2,%3}, {%4,%5,%6,%7}, {%8,%9}, {%0,%1,%2,%3};"
                        : "+f"(C[0]), "+f"(C[1]), "+f"(C[2]), "+f"(C[3])
                        : "r"(A[0]), "r"(A[1]), "r"(A[2]), "r"(A[3]),
                          "r"(bb0), "r"(bb1));
                }
            }
        }

        if (k + 2 < KK) {
            __syncthreads();
            fill(st, gi_next, k + 2);
            asm volatile("cp.async.commit_group;\n");
            gi_next = ld_idx(nbr, is64, gn, (k + 3 < KK) ? (k + 3) : (KK - 1));
        }
    }

    // ---- epilogue ----
    if (which == 0) {
        float ls[8], lq[8];
        #pragma unroll
        for (int j = 0; j < 8; ++j) { ls[j] = 0.f; lq[j] = 0.f; }

        #pragma unroll
        for (int mt = 0; mt < 2; ++mt) {
            int rbase = m0 + wm * 32 + mt * 16 + (lane >> 2);
            bool v0 = rbase < NV, v1 = rbase + 8 < NV;
            #pragma unroll
            for (int nt = 0; nt < 4; ++nt) {
                int col = wn * 32 + nt * 8 + (lane & 3) * 2;
                float* C = acc[mt][nt];
                if (v0) {
                    size_t o = (size_t)rbase * CC + col;
                    *(__half2*)(g_t16 + o) = __floats2half2_rn(C[0], C[1]);
                    ls[nt * 2]     += C[0]; lq[nt * 2]     += C[0] * C[0];
                    ls[nt * 2 + 1] += C[1]; lq[nt * 2 + 1] += C[1] * C[1];
                }
                if (v1) {
                    size_t o = (size_t)(rbase + 8) * CC + col;
                    *(__half2*)(g_t16 + o) = __floats2half2_rn(C[2], C[3]);
                    ls[nt * 2]     += C[2]; lq[nt * 2]     += C[2] * C[2];
                    ls[nt * 2 + 1] += C[3]; lq[nt * 2 + 1] += C[3] * C[3];
                }
            }
        }
        #pragma unroll
        for (int m = 4; m <= 16; m <<= 1) {
            #pragma unroll
            for (int j = 0; j < 8; ++j) {
                ls[j] += __shfl_xor_sync(0xffffffffu, ls[j], m);
                lq[j] += __shfl_xor_sync(0xffffffffu, lq[j], m);
            }
        }
        float* red = (float*)smem;
        __syncthreads();
        if ((lane >> 2) == 0) {
            #pragma unroll
            for (int j = 0; j < 8; ++j) {
                int cl = (j >> 1) * 8 + (lane & 3) * 2 + (j & 1);
                red[warp * 32 + cl]              = ls[j];
                red[NWARP * 32 + warp * 32 + cl] = lq[j];
            }
        }
        __syncthreads();
        if (tid < 128) {
            int part = tid >> 6, c = tid & 63;
            int cwn = c >> 5, cl = c & 31;
            const float* base = red + part * NWARP * 32;
            float v = 0.f;
            #pragma unroll
            for (int i = 0; i < 4; ++i) v += base[(2 * i + cwn) * 32 + cl];
            atomicAdd(part ? &g_sumsq[1][c] : &g_sum[1][c], v);
        }
    } else {
        #pragma unroll
        for (int mt = 0; mt < 2; ++mt) {
            int rbase = m0 + wm * 32 + mt * 16 + (lane >> 2);
            #pragma unroll
            for (int nt = 0; nt < 4; ++nt) {
                int col = wn * 32 + nt * 8 + (lane & 3) * 2;
                float* C = acc[mt][nt];
                if (rbase < NV) {
                    size_t o = (size_t)rbase * CC + col;
                    float2 rv = *(const float2*)(residual + o);
                    float2 v; v.x = C[0] + rv.x; v.y = C[1] + rv.y;
                    *(float2*)(dout + o) = v;
                }
                if (rbase + 8 < NV) {
                    size_t o = (size_t)(rbase + 8) * CC + col;
                    float2 rv = *(const float2*)(residual + o);
                    float2 v; v.x = C[2] + rv.x; v.y = C[3] + rv.y;
                    *(float2*)(dout + o) = v;
                }
            }
        }
    }
}

// ---------------- launch ----------------
extern "C" void kernel_launch(void* const* d_in, const int* in_sizes, int n_in,
                              void* d_out, int out_size) {
    const float* x      = (const float*)d_in[0];
    const void*  nbr    = d_in[1];
    const float* W1     = (const float*)d_in[2];
    const float* gamma1 = (const float*)d_in[3];
    const float* beta1  = (const float*)d_in[4];
    const float* W2     = (const float*)d_in[5];
    const float* gamma2 = (const float*)d_in[6];
    const float* beta2  = (const float*)d_in[7];
    float* out = (float*)d_out;

    const int conv_grid = (NV + BM - 1) / BM;
    const int bn1_grid  = (NV * CC / 8 + 255) / 256;   // 6250

    static int attr_set = 0;
    if (!attr_set) {
        cudaFuncSetAttribute(k_conv, cudaFuncAttributeMaxDynamicSharedMemorySize,
                             SMEM_CONV);
        attr_set = 1;
    }

    k_zero<<<1, 64>>>(nbr);                                   // 1
    k_prep<<<PREP_GRID, 256>>>(x, W1, W2, gamma1, beta1);     // 2
    k_conv<<<conv_grid, NT, SMEM_CONV>>>(nbr, 0, nullptr, nullptr); // 3
    k_bnrelu1<<<bn1_grid, 256>>>(gamma2, beta2);              // 4 <- ncu
    k_conv<<<conv_grid, NT, SMEM_CONV>>>(nbr, 1, x, out);     // 5
}

// round 14
// speedup vs baseline: 1.0052x; 1.0052x over previous
#include <cuda_runtime.h>
#include <cuda_fp16.h>
#include <cstdint>

#define NV 200000
#define KK 27
#define CC 64
#define BM 128
#define NT 256
#define NWARP 8
#define STAGES 2
#define BN_EPS 1e-5f
#define PREP_GRID 740
#define CONV_TILES ((NV + BM - 1) / BM)   // 1563
#define P_GRID 592                        // 148 SMs * 4 CTAs

#define A_BYTES (BM * 128)
#define B_BYTES (CC * 128)
#define STAGE_BYTES (A_BYTES + B_BYTES)            // 24576
#define SMEM_CONV (STAGES * STAGE_BYTES)           // 49152 -> 4 CTAs/SM

#define SW(o) ((o) ^ (((o) >> 3) & 0x70))

// ---------------- device scratch ----------------
__device__ alignas(256) __half g_y[(size_t)NV * CC];
__device__ alignas(256) __half g_t16[(size_t)NV * CC];
__device__ alignas(256) __half g_Wh[2][KK * CC * CC];
__device__ float g_sum[2][CC];
__device__ float g_sumsq[2][CC];
__device__ unsigned g_arrive;
__device__ unsigned g_bar;
__device__ int g_is64;

// ---------------- helpers ----------------
__device__ __forceinline__ uint32_t smem_u32(const void* p) {
    return (uint32_t)__cvta_generic_to_shared(p);
}
__device__ __forceinline__ void cp16(uint32_t dst, const void* src) {
    asm volatile("cp.async.cg.shared.global [%0], [%1], 16;\n" :: "r"(dst), "l"(src));
}
__device__ __forceinline__ int ld_idx(const void* nbr, bool is64, int gn, int k) {
    size_t pos = (size_t)gn * KK + k;
    return is64 ? (int)((const long long*)nbr)[pos] : ((const int*)nbr)[pos];
}

// ---------------- zero stats/counters + detect index dtype ----------------
__global__ void k_zero(const void* __restrict__ nbr) {
    int t = threadIdx.x;
    if (t < CC) {
        g_sum[0][t] = 0.f; g_sum[1][t] = 0.f;
        g_sumsq[0][t] = 0.f; g_sumsq[1][t] = 0.f;
    }
    if (t == 0) {
        g_arrive = 0u;
        g_bar = 0u;
        const long long* p = (const long long*)nbr;
        int ok = 1;
        for (int i = 0; i < 64; ++i) {
            long long v = p[i];
            if (v < 0 || v >= NV) { ok = 0; break; }
        }
        g_is64 = ok;
    }
}

// ---------------- stats0 -> arrive -> wcvt (hidden) -> spin -> bnrelu0 ----------------
__global__ void __launch_bounds__(256, 5)
k_prep(const float* __restrict__ x,
       const float* __restrict__ W1,
       const float* __restrict__ W2,
       const float* __restrict__ gamma1,
       const float* __restrict__ beta1) {
    __shared__ float sh[2][4][CC];
    {
        int ch = threadIdx.x & 63;
        int rg = threadIdx.x >> 6;
        float s = 0.f, s2 = 0.f;
        for (int row = blockIdx.x * 4 + rg; row < NV; row += gridDim.x * 4) {
            float v = x[(size_t)row * CC + ch];
            s += v; s2 += v * v;
        }
        sh[0][rg][ch] = s; sh[1][rg][ch] = s2;
        __syncthreads();
        if (rg == 0) {
            s  = sh[0][0][ch] + sh[0][1][ch] + sh[0][2][ch] + sh[0][3][ch];
            s2 = sh[1][0][ch] + sh[1][1][ch] + sh[1][2][ch] + sh[1][3][ch];
            atomicAdd(&g_sum[0][ch], s);
            atomicAdd(&g_sumsq[0][ch], s2);
        }
    }
    __threadfence();
    __syncthreads();
    if (threadIdx.x == 0) atomicAdd(&g_arrive, 1u);

    // weight conversion — hidden in the sync window
    const int wtotal = KK * CC * CC;
    for (int i = blockIdx.x * blockDim.x + threadIdx.x; i < wtotal;
         i += gridDim.x * blockDim.x) {
        int k  = i >> 12;
        int ci = (i & 4095) >> 6;
        int co = i & 63;
        uint32_t off = (uint32_t)SW(ci * 128 + co * 2) >> 1;
        g_Wh[0][k * 4096 + off] = __float2half_rn(W1[i]);
        g_Wh[1][k * 4096 + off] = __float2half_rn(W2[i]);
    }

    if (threadIdx.x == 0) {
        while (atomicAdd(&g_arrive, 0u) < (unsigned)gridDim.x) {}
    }
    __syncthreads();

    __shared__ float s_scale[CC], s_shift[CC];
    if (threadIdx.x < CC) {
        int c = threadIdx.x;
        float mean = g_sum[0][c] / (float)NV;
        float var  = g_sumsq[0][c] / (float)NV - mean * mean;
        float s = gamma1[c] * rsqrtf(var + BN_EPS);
        s_scale[c] = s;
        s_shift[c] = beta1[c] - mean * s;
    }
    __syncthreads();
    const int total = NV * CC / 8;
    for (int i = blockIdx.x * blockDim.x + threadIdx.x; i < total;
         i += gridDim.x * blockDim.x) {
        int cb = (i & 7) << 3;
        float4 u0 = ((const float4*)x)[2 * i];
        float4 u1 = ((const float4*)x)[2 * i + 1];
        float f[8] = {u0.x, u0.y, u0.z, u0.w, u1.x, u1.y, u1.z, u1.w};
        #pragma unroll
        for (int j = 0; j < 8; ++j)
            f[j] = fmaxf(fmaf(f[j], s_scale[cb + j], s_shift[cb + j]), 0.f);
        uint4 o;
        *(__half2*)&o.x = __floats2half2_rn(f[0], f[1]);
        *(__half2*)&o.y = __floats2half2_rn(f[2], f[3]);
        *(__half2*)&o.z = __floats2half2_rn(f[4], f[5]);
        *(__half2*)&o.w = __floats2half2_rn(f[6], f[7]);
        ((uint4*)g_y)[i] = o;
    }
}

// ---------------- conv1: one tile per CTA, fused stats epilogue ----------------
__global__ void __launch_bounds__(NT, 4)
k_conv1(const void* __restrict__ nbr)
{
    extern __shared__ char smem[];
    const uint32_t sb = smem_u32(smem);
    const __half* __restrict__ Wh = g_Wh[0];

    const int tid = threadIdx.x;
    const int warp = tid >> 5, lane = tid & 31;
    const int wm = warp >> 1, wn = warp & 1;
    const int m0 = blockIdx.x * BM;
    const bool is64 = (g_is64 != 0);

    float acc[2][4][4];
    #pragma unroll
    for (int a = 0; a < 2; ++a)
        #pragma unroll
        for (int b = 0; b < 4; ++b)
            #pragma unroll
            for (int c = 0; c < 4; ++c) acc[a][b][c] = 0.f;

    const int r  = tid >> 1;
    const int hs = tid & 1;
    const int gn = (m0 + r < NV) ? (m0 + r) : 0;

    auto fill = [&](int st, int gi, int k) {
        const __half* srcA = g_y + (size_t)gi * CC + hs * 32;
        uint32_t abase = sb + st * STAGE_BYTES;
        #pragma unroll
        for (int j = 0; j < 4; ++j) {
            uint32_t boff = (uint32_t)(r * 128 + (hs * 4 + j) * 16);
            cp16(abase + SW(boff), srcA + j * 8);
        }
        const __half* srcB = Wh + k * 4096;
        uint32_t bbase = abase + A_BYTES;
        cp16(bbase + tid * 16,        srcB + tid * 8);
        cp16(bbase + (tid + NT) * 16, srcB + (tid + NT) * 8);
    };

    {
        int i0 = ld_idx(nbr, is64, gn, 0);
        int i1 = ld_idx(nbr, is64, gn, 1);
        fill(0, i0, 0);
        asm volatile("cp.async.commit_group;\n");
        fill(1, i1, 1);
        asm volatile("cp.async.commit_group;\n");
    }
    int gi_next = ld_idx(nbr, is64, gn, 2);

    for (int k = 0; k < KK; ++k) {
        const int st = k & 1;
        if (k + 1 < KK)
            asm volatile("cp.async.wait_group 1;\n");
        else
            asm volatile("cp.async.wait_group 0;\n");
        __syncthreads();

        const uint32_t abase = sb + st * STAGE_BYTES;
        const uint32_t bbase = abase + A_BYTES;

        #pragma unroll
        for (int ks = 0; ks < 4; ++ks) {
            const int k0 = ks * 16;
            uint32_t a0[4], a1[4], b0[4], b1[4];
            {
                int row = wm * 32 + (lane & 15);
                int col = k0 + (lane >> 4) * 8;
                uint32_t ad = abase + SW((uint32_t)(row * 128 + col * 2));
                asm volatile("ldmatrix.sync.aligned.m8n8.x4.shared.b16 {%0,%1,%2,%3}, [%4];"
                             : "=r"(a0[0]), "=r"(a0[1]), "=r"(a0[2]), "=r"(a0[3]) : "r"(ad));
                ad = abase + SW((uint32_t)((row + 16) * 128 + col * 2));
                asm volatile("ldmatrix.sync.aligned.m8n8.x4.shared.b16 {%0,%1,%2,%3}, [%4];"
                             : "=r"(a1[0]), "=r"(a1[1]), "=r"(a1[2]), "=r"(a1[3]) : "r"(ad));
            }
            {
                int krow = k0 + ((lane >> 3) & 1) * 8 + (lane & 7);
                int coll = wn * 32 + (lane >> 4) * 8;
                uint32_t ad = bbase + SW((uint32_t)(krow * 128 + coll * 2));
                asm volatile("ldmatrix.sync.aligned.m8n8.x4.trans.shared.b16 {%0,%1,%2,%3}, [%4];"
                             : "=r"(b0[0]), "=r"(b0[1]), "=r"(b0[2]), "=r"(b0[3]) : "r"(ad));
                ad = bbase + SW((uint32_t)(krow * 128 + (coll + 16) * 2));
                asm volatile("ldmatrix.sync.aligned.m8n8.x4.trans.shared.b16 {%0,%1,%2,%3}, [%4];"
                             : "=r"(b1[0]), "=r"(b1[1]), "=r"(b1[2]), "=r"(b1[3]) : "r"(ad));
            }
            #pragma unroll
            for (int mt = 0; mt < 2; ++mt) {
                const uint32_t* A = mt ? a1 : a0;
                #pragma unroll
                for (int nt = 0; nt < 4; ++nt) {
                    const uint32_t* B = (nt < 2) ? b0 : b1;
                    uint32_t bb0 = B[(nt & 1) * 2], bb1 = B[(nt & 1) * 2 + 1];
                    float* C = acc[mt][nt];
                    asm volatile(
                        "mma.sync.aligned.m16n8k16.row.col.f32.f16.f16.f32 "
                        "{%0,%1,%2,%3}, {%4,%5,%6,%7}, {%8,%9}, {%0,%1,%2,%3};"
                        : "+f"(C[0]), "+f"(C[1]), "+f"(C[2]), "+f"(C[3])
                        : "r"(A[0]), "r"(A[1]), "r"(A[2]), "r"(A[3]),
                          "r"(bb0), "r"(bb1));
                }
            }
        }

        if (k + 2 < KK) {
            __syncthreads();
            fill(st, gi_next, k + 2);
            asm volatile("cp.async.commit_group;\n");
            gi_next = ld_idx(nbr, is64, gn, (k + 3 < KK) ? (k + 3) : (KK - 1));
        }
    }

    // epilogue: write fp16 + fused stats
    float ls[8], lq[8];
    #pragma unroll
    for (int j = 0; j < 8; ++j) { ls[j] = 0.f; lq[j] = 0.f; }

    #pragma unroll
    for (int mt = 0; mt < 2; ++mt) {
        int rbase = m0 + wm * 32 + mt * 16 + (lane >> 2);
        bool v0 = rbase < NV, v1 = rbase + 8 < NV;
        #pragma unroll
        for (int nt = 0; nt < 4; ++nt) {
            int col = wn * 32 + nt * 8 + (lane & 3) * 2;
            float* C = acc[mt][nt];
            if (v0) {
                size_t o = (size_t)rbase * CC + col;
                *(__half2*)(g_t16 + o) = __floats2half2_rn(C[0], C[1]);
                ls[nt * 2]     += C[0]; lq[nt * 2]     += C[0] * C[0];
                ls[nt * 2 + 1] += C[1]; lq[nt * 2 + 1] += C[1] * C[1];
            }
            if (v1) {
                size_t o = (size_t)(rbase + 8) * CC + col;
                *(__half2*)(g_t16 + o) = __floats2half2_rn(C[2], C[3]);
                ls[nt * 2]     += C[2]; lq[nt * 2]     += C[2] * C[2];
                ls[nt * 2 + 1] += C[3]; lq[nt * 2 + 1] += C[3] * C[3];
            }
        }
    }
    #pragma unroll
    for (int m = 4; m <= 16; m <<= 1) {
        #pragma unroll
        for (int j = 0; j < 8; ++j) {
            ls[j] += __shfl_xor_sync(0xffffffffu, ls[j], m);
            lq[j] += __shfl_xor_sync(0xffffffffu, lq[j], m);
        }
    }
    float* red = (float*)smem;
    __syncthreads();
    if ((lane >> 2) == 0) {
        #pragma unroll
        for (int j = 0; j < 8; ++j) {
            int cl = (j >> 1) * 8 + (lane & 3) * 2 + (j & 1);
            red[warp * 32 + cl]              = ls[j];
            red[NWARP * 32 + warp * 32 + cl] = lq[j];
        }
    }
    __syncthreads();
    if (tid < 128) {
        int part = tid >> 6, c = tid & 63;
        int cwn = c >> 5, cl = c & 31;
        const float* base = red + part * NWARP * 32;
        float v = 0.f;
        #pragma unroll
        for (int i = 0; i < 4; ++i) v += base[(2 * i + cwn) * 32 + cl];
        atomicAdd(part ? &g_sumsq[1][c] : &g_sum[1][c], v);
    }
}

// ---------------- conv2 persistent: bnrelu1 phase + grid barrier + conv tiles ----------------
__global__ void __launch_bounds__(NT, 4)
k_conv2p(const void* __restrict__ nbr,
         const float* __restrict__ residual, float* __restrict__ dout,
         const float* __restrict__ gamma2, const float* __restrict__ beta2)
{
    extern __shared__ char smem[];
    const uint32_t sb = smem_u32(smem);
    const __half* __restrict__ Wh = g_Wh[1];

    const int tid = threadIdx.x;
    const int warp = tid >> 5, lane = tid & 31;
    const int wm = warp >> 1, wn = warp & 1;
    const bool is64 = (g_is64 != 0);

    // ---- phase 1: BN2 + ReLU rewrite g_t16 -> g_y ----
    {
        __shared__ float s_scale[CC], s_shift[CC];
        if (tid < CC) {
            int c = tid;
            float mean = g_sum[1][c] / (float)NV;
            float var  = g_sumsq[1][c] / (float)NV - mean * mean;
            float s = gamma2[c] * rsqrtf(var + BN_EPS);
            s_scale[c] = s;
            s_shift[c] = beta2[c] - mean * s;
        }
        __syncthreads();
        const int total = NV * CC / 8;
        for (int i = blockIdx.x * blockDim.x + tid; i < total;
             i += gridDim.x * blockDim.x) {
            int cb = (i & 7) << 3;
            uint4 u = ((const uint4*)g_t16)[i];
            float2 p0 = __half22float2(*(__half2*)&u.x);
            float2 p1 = __half22float2(*(__half2*)&u.y);
            float2 p2 = __half22float2(*(__half2*)&u.z);
            float2 p3 = __half22float2(*(__half2*)&u.w);
            float f[8] = {p0.x, p0.y, p1.x, p1.y, p2.x, p2.y, p3.x, p3.y};
            #pragma unroll
            for (int j = 0; j < 8; ++j)
                f[j] = fmaxf(fmaf(f[j], s_scale[cb + j], s_shift[cb + j]), 0.f);
            uint4 o;
            *(__half2*)&o.x = __floats2half2_rn(f[0], f[1]);
            *(__half2*)&o.y = __floats2half2_rn(f[2], f[3]);
            *(__half2*)&o.z = __floats2half2_rn(f[4], f[5]);
            *(__half2*)&o.w = __floats2half2_rn(f[6], f[7]);
            ((uint4*)g_y)[i] = o;
        }
    }

    // ---- grid barrier (all P_GRID CTAs resident: grid == 4 CTAs/SM capacity) ----
    __threadfence();
    __syncthreads();
    if (tid == 0) {
        atomicAdd(&g_bar, 1u);
        while (atomicAdd(&g_bar, 0u) < (unsigned)gridDim.x) {}
    }
    __syncthreads();

    // ---- phase 2: conv tiles, persistent ----
    for (int tile = blockIdx.x; tile < CONV_TILES; tile += gridDim.x) {
        const int m0 = tile * BM;

        float acc[2][4][4];
        #pragma unroll
        for (int a = 0; a < 2; ++a)
            #pragma unroll
            for (int b = 0; b < 4; ++b)
                #pragma unroll
                for (int c = 0; c < 4; ++c) acc[a][b][c] = 0.f;

        const int r  = tid >> 1;
        const int hs = tid & 1;
        const int gn = (m0 + r < NV) ? (m0 + r) : 0;

        auto fill = [&](int st, int gi, int k) {
            const __half* srcA = g_y + (size_t)gi * CC + hs * 32;
            uint32_t abase = sb + st * STAGE_BYTES;
            #pragma unroll
            for (int j = 0; j < 4; ++j) {
                uint32_t boff = (uint32_t)(r * 128 + (hs * 4 + j) * 16);
                cp16(abase + SW(boff), srcA + j * 8);
            }
            const __half* srcB = Wh + k * 4096;
            uint32_t bbase = abase + A_BYTES;
            cp16(bbase + tid * 16,        srcB + tid * 8);
            cp16(bbase + (tid + NT) * 16, srcB + (tid + NT) * 8);
        };

        {
            int i0 = ld_idx(nbr, is64, gn, 0);
            int i1 = ld_idx(nbr, is64, gn, 1);
            fill(0, i0, 0);
            asm volatile("cp.async.commit_group;\n");
            fill(1, i1, 1);
            asm volatile("cp.async.commit_group;\n");
        }
        int gi_next = ld_idx(nbr, is64, gn, 2);

        for (int k = 0; k < KK; ++k) {
            const int st = k & 1;
            if (k + 1 < KK)
                asm volatile("cp.async.wait_group 1;\n");
            else
                asm volatile("cp.async.wait_group 0;\n");
            __syncthreads();

            const uint32_t abase = sb + st * STAGE_BYTES;
            const uint32_t bbase = abase + A_BYTES;

            #pragma unroll
            for (int ks = 0; ks < 4; ++ks) {
                const int k0 = ks * 16;
                uint32_t a0[4], a1[4], b0[4], b1[4];
                {
                    int row = wm * 32 + (lane & 15);
                    int col = k0 + (lane >> 4) * 8;
                    uint32_t ad = abase + SW((uint32_t)(row * 128 + col * 2));
                    asm volatile("ldmatrix.sync.aligned.m8n8.x4.shared.b16 {%0,%1,%2,%3}, [%4];"
                                 : "=r"(a0[0]), "=r"(a0[1]), "=r"(a0[2]), "=r"(a0[3]) : "r"(ad));
                    ad = abase + SW((uint32_t)((row + 16) * 128 + col * 2));
                    asm volatile("ldmatrix.sync.aligned.m8n8.x4.shared.b16 {%0,%1,%2,%3}, [%4];"
                                 : "=r"(a1[0]), "=r"(a1[1]), "=r"(a1[2]), "=r"(a1[3]) : "r"(ad));
                }
                {
                    int krow = k0 + ((lane >> 3) & 1) * 8 + (lane & 7);
                    int coll = wn * 32 + (lane >> 4) * 8;
                    uint32_t ad = bbase + SW((uint32_t)(krow * 128 + coll * 2));
                    asm volatile("ldmatrix.sync.aligned.m8n8.x4.trans.shared.b16 {%0,%1,%2,%3}, [%4];"
                                 : "=r"(b0[0]), "=r"(b0[1]), "=r"(b0[2]), "=r"(b0[3]) : "r"(ad));
                    ad = bbase + SW((uint32_t)(krow * 128 + (coll + 16) * 2));
                    asm volatile("ldmatrix.sync.aligned.m8n8.x4.trans.shared.b16 {%0,%1,%2,%3}, [%4];"
                                 : "=r"(b1[0]), "=r"(b1[1]), "=r"(b1[2]), "=r"(b1[3]) : "r"(ad));
                }
                #pragma unroll
                for (int mt = 0; mt < 2; ++mt) {
                    const uint32_t* A = mt ? a1 : a0;
                    #pragma unroll
                    for (int nt = 0; nt < 4; ++nt) {
                        const uint32_t* B = (nt < 2) ? b0 : b1;
                        uint32_t bb0 = B[(nt & 1) * 2], bb1 = B[(nt & 1) * 2 + 1];
                        float* C = acc[mt][nt];
                        asm volatile(
                            "mma.sync.aligned.m16n8k16.row.col.f32.f16.f16.f32 "
                            "{%0,%1,%2,%3}, {%4,%5,%6,%7}, {%8,%9}, {%0,%1,%2,%3};"
                            : "+f"(C[0]), "+f"(C[1]), "+f"(C[2]), "+f"(C[3])
                            : "r"(A[0]), "r"(A[1]), "r"(A[2]), "r"(A[3]),
                              "r"(bb0), "r"(bb1));
                    }
                }
            }

            if (k + 2 < KK) {
                __syncthreads();
                fill(st, gi_next, k + 2);
                asm volatile("cp.async.commit_group;\n");
                gi_next = ld_idx(nbr, is64, gn, (k + 3 < KK) ? (k + 3) : (KK - 1));
            }
        }

        // epilogue: fp32 out + residual
        #pragma unroll
        for (int mt = 0; mt < 2; ++mt) {
            int rbase = m0 + wm * 32 + mt * 16 + (lane >> 2);
            #pragma unroll
            for (int nt = 0; nt < 4; ++nt) {
                int col = wn * 32 + nt * 8 + (lane & 3) * 2;
                float* C = acc[mt][nt];
                if (rbase < NV) {
                    size_t o = (size_t)rbase * CC + col;
                    float2 rv = *(const float2*)(residual + o);
                    float2 v; v.x = C[0] + rv.x; v.y = C[1] + rv.y;
                    *(float2*)(dout + o) = v;
                }
                if (rbase + 8 < NV) {
                    size_t o = (size_t)(rbase + 8) * CC + col;
                    float2 rv = *(const float2*)(residual + o);
                    float2 v; v.x = C[2] + rv.x; v.y = C[3] + rv.y;
                    *(float2*)(dout + o) = v;
                }
            }
        }
        __syncthreads();   // protect smem reuse across tiles
    }
}

// ---------------- launch ----------------
extern "C" void kernel_launch(void* const* d_in, const int* in_sizes, int n_in,
                              void* d_out, int out_size) {
    const float* x      = (const float*)d_in[0];
    const void*  nbr    = d_in[1];
    const float* W1     = (const float*)d_in[2];
    const float* gamma1 = (const float*)d_in[3];
    const float* beta1  = (const float*)d_in[4];
    const float* W2     = (const float*)d_in[5];
    const float* gamma2 = (const float*)d_in[6];
    const float* beta2  = (const float*)d_in[7];
    float* out = (float*)d_out;

    static int attr_set = 0;
    if (!attr_set) {
        cudaFuncSetAttribute(k_conv1, cudaFuncAttributeMaxDynamicSharedMemorySize,
                             SMEM_CONV);
        cudaFuncSetAttribute(k_conv2p, cudaFuncAttributeMaxDynamicSharedMemorySize,
                             SMEM_CONV);
        attr_set = 1;
    }

    k_zero<<<1, 64>>>(nbr);                                     // 1
    k_prep<<<PREP_GRID, 256>>>(x, W1, W2, gamma1, beta1);       // 2
    k_conv1<<<CONV_TILES, NT, SMEM_CONV>>>(nbr);                // 3
    k_conv2p<<<P_GRID, NT, SMEM_CONV>>>(nbr, x, out, gamma2, beta2); // 4 <- ncu
}

// round 15
// speedup vs baseline: 1.0233x; 1.0181x over previous
#include <cuda_runtime.h>
#include <cuda_fp16.h>
#include <cstdint>

#define NV 200000
#define KK 27
#define CC 64
#define BM 128
#define NT 256
#define NWARP 8
#define STAGES 2
#define BN_EPS 1e-5f
#define PREP_GRID 740

#define A_BYTES (BM * 128)
#define B_BYTES (CC * 128)
#define STAGE_BYTES (A_BYTES + B_BYTES)            // 24576
#define SMEM_CONV (STAGES * STAGE_BYTES)           // 49152 -> 4 CTAs/SM

#define SW(o) ((o) ^ (((o) >> 3) & 0x70))

// ---------------- device scratch ----------------
__device__ alignas(256) __half g_y[(size_t)NV * CC];
__device__ alignas(256) __half g_t16[(size_t)NV * CC];
__device__ alignas(256) __half g_Wh[2][KK * CC * CC];
__device__ float g_sum[2][CC];
__device__ float g_sumsq[2][CC];
__device__ unsigned g_arrive;
__device__ int g_is64;

// ---------------- helpers ----------------
__device__ __forceinline__ uint32_t smem_u32(const void* p) {
    return (uint32_t)__cvta_generic_to_shared(p);
}
__device__ __forceinline__ void cp16(uint32_t dst, const void* src) {
    asm volatile("cp.async.cg.shared.global [%0], [%1], 16;\n" :: "r"(dst), "l"(src));
}
__device__ __forceinline__ int ld_idx(const void* nbr, bool is64, int gn, int k) {
    size_t pos = (size_t)gn * KK + k;
    return is64 ? (int)((const long long*)nbr)[pos] : ((const int*)nbr)[pos];
}

// ---------------- zero stats/counter + detect index dtype ----------------
__global__ void k_zero(const void* __restrict__ nbr) {
    int t = threadIdx.x;
    if (t < CC) {
        g_sum[0][t] = 0.f; g_sum[1][t] = 0.f;
        g_sumsq[0][t] = 0.f; g_sumsq[1][t] = 0.f;
    }
    if (t == 0) {
        g_arrive = 0u;
        const long long* p = (const long long*)nbr;
        int ok = 1;
        for (int i = 0; i < 64; ++i) {
            long long v = p[i];
            if (v < 0 || v >= NV) { ok = 0; break; }
        }
        g_is64 = ok;
    }
}

// ---------------- stats0 -> arrive -> wcvt (hidden) -> spin -> bnrelu0 ----------------
__global__ void __launch_bounds__(256, 5)
k_prep(const float* __restrict__ x,
       const float* __restrict__ W1,
       const float* __restrict__ W2,
       const float* __restrict__ gamma1,
       const float* __restrict__ beta1) {
    __shared__ float sh[2][4][CC];
    {
        int ch = threadIdx.x & 63;
        int rg = threadIdx.x >> 6;
        float s = 0.f, s2 = 0.f;
        for (int row = blockIdx.x * 4 + rg; row < NV; row += gridDim.x * 4) {
            float v = x[(size_t)row * CC + ch];
            s += v; s2 += v * v;
        }
        sh[0][rg][ch] = s; sh[1][rg][ch] = s2;
        __syncthreads();
        if (rg == 0) {
            s  = sh[0][0][ch] + sh[0][1][ch] + sh[0][2][ch] + sh[0][3][ch];
            s2 = sh[1][0][ch] + sh[1][1][ch] + sh[1][2][ch] + sh[1][3][ch];
            atomicAdd(&g_sum[0][ch], s);
            atomicAdd(&g_sumsq[0][ch], s2);
        }
    }
    __threadfence();
    __syncthreads();
    if (threadIdx.x == 0) atomicAdd(&g_arrive, 1u);

    // weight conversion — hidden in the sync window
    const int wtotal = KK * CC * CC;
    for (int i = blockIdx.x * blockDim.x + threadIdx.x; i < wtotal;
         i += gridDim.x * blockDim.x) {
        int k  = i >> 12;
        int ci = (i & 4095) >> 6;
        int co = i & 63;
        uint32_t off = (uint32_t)SW(ci * 128 + co * 2) >> 1;
        g_Wh[0][k * 4096 + off] = __float2half_rn(W1[i]);
        g_Wh[1][k * 4096 + off] = __float2half_rn(W2[i]);
    }

    if (threadIdx.x == 0) {
        while (atomicAdd(&g_arrive, 0u) < (unsigned)gridDim.x) {}
    }
    __syncthreads();

    __shared__ float s_scale[CC], s_shift[CC];
    if (threadIdx.x < CC) {
        int c = threadIdx.x;
        float mean = g_sum[0][c] / (float)NV;
        float var  = g_sumsq[0][c] / (float)NV - mean * mean;
        float s = gamma1[c] * rsqrtf(var + BN_EPS);
        s_scale[c] = s;
        s_shift[c] = beta1[c] - mean * s;
    }
    __syncthreads();
    const int total = NV * CC / 8;
    for (int i = blockIdx.x * blockDim.x + threadIdx.x; i < total;
         i += gridDim.x * blockDim.x) {
        int cb = (i & 7) << 3;
        float4 u0 = ((const float4*)x)[2 * i];
        float4 u1 = ((const float4*)x)[2 * i + 1];
        float f[8] = {u0.x, u0.y, u0.z, u0.w, u1.x, u1.y, u1.z, u1.w};
        #pragma unroll
        for (int j = 0; j < 8; ++j)
            f[j] = fmaxf(fmaf(f[j], s_scale[cb + j], s_shift[cb + j]), 0.f);
        uint4 o;
        *(__half2*)&o.x = __floats2half2_rn(f[0], f[1]);
        *(__half2*)&o.y = __floats2half2_rn(f[2], f[3]);
        *(__half2*)&o.z = __floats2half2_rn(f[4], f[5]);
        *(__half2*)&o.w = __floats2half2_rn(f[6], f[7]);
        ((uint4*)g_y)[i] = o;
    }
}

// ---------------- bnrelu stage1: g_t16 -> BN2+ReLU -> g_y ----------------
__global__ void k_bnrelu1(const float* __restrict__ gamma,
                          const float* __restrict__ beta) {
    __shared__ float s_scale[CC], s_shift[CC];
    if (threadIdx.x < CC) {
        int c = threadIdx.x;
        float mean = g_sum[1][c] / (float)NV;
        float var  = g_sumsq[1][c] / (float)NV - mean * mean;
        float s = gamma[c] * rsqrtf(var + BN_EPS);
        s_scale[c] = s;
        s_shift[c] = beta[c] - mean * s;
    }
    __syncthreads();
    const int i = blockIdx.x * blockDim.x + threadIdx.x;
    if (i >= NV * CC / 8) return;
    int cb = (i & 7) << 3;
    uint4 u = ((const uint4*)g_t16)[i];
    float2 p0 = __half22float2(*(__half2*)&u.x);
    float2 p1 = __half22float2(*(__half2*)&u.y);
    float2 p2 = __half22float2(*(__half2*)&u.z);
    float2 p3 = __half22float2(*(__half2*)&u.w);
    float f[8] = {p0.x, p0.y, p1.x, p1.y, p2.x, p2.y, p3.x, p3.y};
    #pragma unroll
    for (int j = 0; j < 8; ++j)
        f[j] = fmaxf(fmaf(f[j], s_scale[cb + j], s_shift[cb + j]), 0.f);
    uint4 o;
    *(__half2*)&o.x = __floats2half2_rn(f[0], f[1]);
    *(__half2*)&o.y = __floats2half2_rn(f[2], f[3]);
    *(__half2*)&o.z = __floats2half2_rn(f[4], f[5]);
    *(__half2*)&o.w = __floats2half2_rn(f[6], f[7]);
    ((uint4*)g_y)[i] = o;
}

// ---------------- gather-GEMM conv: BM=128, 8 warps (4m x 2n, m32n32), occ 4 ----------------
__global__ void __launch_bounds__(NT, 4)
k_conv(const void* __restrict__ nbr, int which,
       const float* __restrict__ residual, float* __restrict__ dout)
{
    extern __shared__ char smem[];
    const uint32_t sb = smem_u32(smem);
    const __half* __restrict__ Wh = g_Wh[which];

    const int tid = threadIdx.x;
    const int warp = tid >> 5, lane = tid & 31;
    const int wm = warp >> 1, wn = warp & 1;
    const int m0 = blockIdx.x * BM;
    const bool is64 = (g_is64 != 0);

    float acc[2][4][4];
    #pragma unroll
    for (int a = 0; a < 2; ++a)
        #pragma unroll
        for (int b = 0; b < 4; ++b)
            #pragma unroll
            for (int c = 0; c < 4; ++c) acc[a][b][c] = 0.f;

    const int r  = tid >> 1;
    const int hs = tid & 1;
    const int gn = (m0 + r < NV) ? (m0 + r) : 0;

    auto fill = [&](int st, int gi, int k) {
        const __half* srcA = g_y + (size_t)gi * CC + hs * 32;
        uint32_t abase = sb + st * STAGE_BYTES;
        #pragma unroll
        for (int j = 0; j < 4; ++j) {
            uint32_t boff = (uint32_t)(r * 128 + (hs * 4 + j) * 16);
            cp16(abase + SW(boff), srcA + j * 8);
        }
        const __half* srcB = Wh + k * 4096;
        uint32_t bbase = abase + A_BYTES;
        cp16(bbase + tid * 16,        srcB + tid * 8);
        cp16(bbase + (tid + NT) * 16, srcB + (tid + NT) * 8);
    };

    {
        int i0 = ld_idx(nbr, is64, gn, 0);
        int i1 = ld_idx(nbr, is64, gn, 1);
        fill(0, i0, 0);
        asm volatile("cp.async.commit_group;\n");
        fill(1, i1, 1);
        asm volatile("cp.async.commit_group;\n");
    }
    int gi_next = ld_idx(nbr, is64, gn, 2);

    for (int k = 0; k < KK; ++k) {
        const int st = k & 1;
        if (k + 1 < KK)
            asm volatile("cp.async.wait_group 1;\n");
        else
            asm volatile("cp.async.wait_group 0;\n");
        __syncthreads();

        const uint32_t abase = sb + st * STAGE_BYTES;
        const uint32_t bbase = abase + A_BYTES;

        #pragma unroll
        for (int ks = 0; ks < 4; ++ks) {
            const int k0 = ks * 16;
            uint32_t a0[4], a1[4], b0[4], b1[4];
            {
                int row = wm * 32 + (lane & 15);
                int col = k0 + (lane >> 4) * 8;
                uint32_t ad = abase + SW((uint32_t)(row * 128 + col * 2));
                asm volatile("ldmatrix.sync.aligned.m8n8.x4.shared.b16 {%0,%1,%2,%3}, [%4];"
                             : "=r"(a0[0]), "=r"(a0[1]), "=r"(a0[2]), "=r"(a0[3]) : "r"(ad));
                ad = abase + SW((uint32_t)((row + 16) * 128 + col * 2));
                asm volatile("ldmatrix.sync.aligned.m8n8.x4.shared.b16 {%0,%1,%2,%3}, [%4];"
                             : "=r"(a1[0]), "=r"(a1[1]), "=r"(a1[2]), "=r"(a1[3]) : "r"(ad));
            }
            {
                int krow = k0 + ((lane >> 3) & 1) * 8 + (lane & 7);
                int coll = wn * 32 + (lane >> 4) * 8;
                uint32_t ad = bbase + SW((uint32_t)(krow * 128 + coll * 2));
                asm volatile("ldmatrix.sync.aligned.m8n8.x4.trans.shared.b16 {%0,%1,%2,%3}, [%4];"
                             : "=r"(b0[0]), "=r"(b0[1]), "=r"(b0[2]), "=r"(b0[3]) : "r"(ad));
                ad = bbase + SW((uint32_t)(krow * 128 + (coll + 16) * 2));
                asm volatile("ldmatrix.sync.aligned.m8n8.x4.trans.shared.b16 {%0,%1,%2,%3}, [%4];"
                             : "=r"(b1[0]), "=r"(b1[1]), "=r"(b1[2]), "=r"(b1[3]) : "r"(ad));
            }
            #pragma unroll
            for (int mt = 0; mt < 2; ++mt) {
                const uint32_t* A = mt ? a1 : a0;
                #pragma unroll
                for (int nt = 0; nt < 4; ++nt) {
                    const uint32_t* B = (nt < 2) ? b0 : b1;
                    uint32_t bb0 = B[(nt & 1) * 2], bb1 = B[(nt & 1) * 2 + 1];
                    float* C = acc[mt][nt];
                    asm volatile(
                        "mma.sync.aligned.m16n8k16.row.col.f32.f16.f16.f32 "
                        "{%0,%1,%2,%3}, {%4,%5,%6,%7}, {%8,%9}, {%0,%1,%2,%3};"
                        : "+f"(C[0]), "+f"(C[1]), "+f"(C[2]), "+f"(C[3])
                        : "r"(A[0]), "r"(A[1]), "r"(A[2]), "r"(A[3]),
                          "r"(bb0), "r"(bb1));
                }
            }
        }

        if (k + 2 < KK) {
            __syncthreads();
            fill(st, gi_next, k + 2);
            asm volatile("cp.async.commit_group;\n");
            gi_next = ld_idx(nbr, is64, gn, (k + 3 < KK) ? (k + 3) : (KK - 1));
        }
    }

    // ---- epilogue ----
    if (which == 0) {
        float ls[8], lq[8];
        #pragma unroll
        for (int j = 0; j < 8; ++j) { ls[j] = 0.f; lq[j] = 0.f; }

        #pragma unroll
        for (int mt = 0; mt < 2; ++mt) {
            int rbase = m0 + wm * 32 + mt * 16 + (lane >> 2);
            bool v0 = rbase < NV, v1 = rbase + 8 < NV;
            #pragma unroll
            for (int nt = 0; nt < 4; ++nt) {
                int col = wn * 32 + nt * 8 + (lane & 3) * 2;
                float* C = acc[mt][nt];
                if (v0) {
                    size_t o = (size_t)rbase * CC + col;
                    *(__half2*)(g_t16 + o) = __floats2half2_rn(C[0], C[1]);
                    ls[nt * 2]     += C[0]; lq[nt * 2]     += C[0] * C[0];
                    ls[nt * 2 + 1] += C[1]; lq[nt * 2 + 1] += C[1] * C[1];
                }
                if (v1) {
                    size_t o = (size_t)(rbase + 8) * CC + col;
                    *(__half2*)(g_t16 + o) = __floats2half2_rn(C[2], C[3]);
                    ls[nt * 2]     += C[2]; lq[nt * 2]     += C[2] * C[2];
                    ls[nt * 2 + 1] += C[3]; lq[nt * 2 + 1] += C[3] * C[3];
                }
            }
        }
        #pragma unroll
        for (int m = 4; m <= 16; m <<= 1) {
            #pragma unroll
            for (int j = 0; j < 8; ++j) {
                ls[j] += __shfl_xor_sync(0xffffffffu, ls[j], m);
                lq[j] += __shfl_xor_sync(0xffffffffu, lq[j], m);
            }
        }
        float* red = (float*)smem;
        __syncthreads();
        if ((lane >> 2) == 0) {
            #pragma unroll
            for (int j = 0; j < 8; ++j) {
                int cl = (j >> 1) * 8 + (lane & 3) * 2 + (j & 1);
                red[warp * 32 + cl]              = ls[j];
                red[NWARP * 32 + warp * 32 + cl] = lq[j];
            }
        }
        __syncthreads();
        if (tid < 128) {
            int part = tid >> 6, c = tid & 63;
            int cwn = c >> 5, cl = c & 31;
            const float* base = red + part * NWARP * 32;
            float v = 0.f;
            #pragma unroll
            for (int i = 0; i < 4; ++i) v += base[(2 * i + cwn) * 32 + cl];
            atomicAdd(part ? &g_sumsq[1][c] : &g_sum[1][c], v);
        }
    } else {
        #pragma unroll
        for (int mt = 0; mt < 2; ++mt) {
            int rbase = m0 + wm * 32 + mt * 16 + (lane >> 2);
            #pragma unroll
            for (int nt = 0; nt < 4; ++nt) {
                int col = wn * 32 + nt * 8 + (lane & 3) * 2;
                float* C = acc[mt][nt];
                if (rbase < NV) {
                    size_t o = (size_t)rbase * CC + col;
                    float2 rv = *(const float2*)(residual + o);
                    float2 v; v.x = C[0] + rv.x; v.y = C[1] + rv.y;
                    *(float2*)(dout + o) = v;
                }
                if (rbase + 8 < NV) {
                    size_t o = (size_t)(rbase + 8) * CC + col;
                    float2 rv = *(const float2*)(residual + o);
                    float2 v; v.x = C[2] + rv.x; v.y = C[3] + rv.y;
                    *(float2*)(dout + o) = v;
                }
            }
        }
    }
}

// ---------------- launch ----------------
extern "C" void kernel_launch(void* const* d_in, const int* in_sizes, int n_in,
                              void* d_out, int out_size) {
    const float* x      = (const float*)d_in[0];
    const void*  nbr    = d_in[1];
    const float* W1     = (const float*)d_in[2];
    const float* gamma1 = (const float*)d_in[3];
    const float* beta1  = (const float*)d_in[4];
    const float* W2     = (const float*)d_in[5];
    const float* gamma2 = (const float*)d_in[6];
    const float* beta2  = (const float*)d_in[7];
    float* out = (float*)d_out;

    const int conv_grid = (NV + BM - 1) / BM;          // 1563
    const int bn1_grid  = (NV * CC / 8 + 255) / 256;   // 6250

    static int attr_set = 0;
    if (!attr_set) {
        cudaFuncSetAttribute(k_conv, cudaFuncAttributeMaxDynamicSharedMemorySize,
                             SMEM_CONV);
        attr_set = 1;
    }

    k_zero<<<1, 64>>>(nbr);                                   // 1
    k_prep<<<PREP_GRID, 256>>>(x, W1, W2, gamma1, beta1);     // 2
    k_conv<<<conv_grid, NT, SMEM_CONV>>>(nbr, 0, nullptr, nullptr); // 3
    k_bnrelu1<<<bn1_grid, 256>>>(gamma2, beta2);              // 4 <- ncu
    k_conv<<<conv_grid, NT, SMEM_CONV>>>(nbr, 1, x, out);     // 5
}

// round 16
// speedup vs baseline: 1.0754x; 1.0508x over previous
#include <cuda_runtime.h>
#include <cuda_fp16.h>
#include <cstdint>

#define NV 200000
#define KK 27
#define CC 64
#define BM 128
#define NT 256
#define NWARP 8
#define STAGES 2
#define BN_EPS 1e-5f
#define PREP_GRID 740

#define A_BYTES (BM * 128)
#define B_BYTES (CC * 128)
#define STAGE_BYTES (A_BYTES + B_BYTES)            // 24576
#define SMEM_CONV (STAGES * STAGE_BYTES)           // 49152 -> 4 CTAs/SM

#define SW(o) ((o) ^ (((o) >> 3) & 0x70))

// ---------------- device scratch ----------------
__device__ alignas(256) __half g_y[(size_t)NV * CC];
__device__ alignas(256) __half g_t16[(size_t)NV * CC];
__device__ alignas(256) __half g_Wh[2][KK * CC * CC];

struct Stats {
    float sum[2][CC];
    float sumsq[2][CC];
    unsigned arrive;
};
__device__ Stats g_st;          // zeroed via cudaMemsetAsync each call
__device__ int g_is64;          // written by k_prep block 0

// ---------------- helpers ----------------
__device__ __forceinline__ uint32_t smem_u32(const void* p) {
    return (uint32_t)__cvta_generic_to_shared(p);
}
__device__ __forceinline__ void cp16(uint32_t dst, const void* src) {
    asm volatile("cp.async.cg.shared.global [%0], [%1], 16;\n" :: "r"(dst), "l"(src));
}
__device__ __forceinline__ int ld_idx(const void* nbr, bool is64, int gn, int k) {
    size_t pos = (size_t)gn * KK + k;
    return is64 ? (int)((const long long*)nbr)[pos] : ((const int*)nbr)[pos];
}

// ---------------- stats0 (MLP4) -> arrive -> wcvt (hidden) -> spin -> bnrelu0 ----------------
__global__ void __launch_bounds__(256, 5)
k_prep(const float* __restrict__ x,
       const float* __restrict__ W1,
       const float* __restrict__ W2,
       const float* __restrict__ gamma1,
       const float* __restrict__ beta1,
       const void* __restrict__ nbr) {
    // index-dtype detection (needed by convs, which run after prep)
    if (blockIdx.x == 0 && threadIdx.x == 0) {
        const long long* p = (const long long*)nbr;
        int ok = 1;
        for (int i = 0; i < 64; ++i) {
            long long v = p[i];
            if (v < 0 || v >= NV) { ok = 0; break; }
        }
        g_is64 = ok;
    }

    // phase A: column stats over x, 4 independent loads in flight
    __shared__ float sh[2][4][CC];
    {
        int ch = threadIdx.x & 63;
        int rg = threadIdx.x >> 6;
        const int G = gridDim.x * 4;
        float s = 0.f, s2 = 0.f;
        int row = blockIdx.x * 4 + rg;
        for (; row + 3 * G < NV; row += 4 * G) {
            float v0 = x[(size_t)row * CC + ch];
            float v1 = x[(size_t)(row + G) * CC + ch];
            float v2 = x[(size_t)(row + 2 * G) * CC + ch];
            float v3 = x[(size_t)(row + 3 * G) * CC + ch];
            s  += (v0 + v1) + (v2 + v3);
            s2 += ((v0 * v0 + v1 * v1) + (v2 * v2 + v3 * v3));
        }
        for (; row < NV; row += G) {
            float v = x[(size_t)row * CC + ch];
            s += v; s2 += v * v;
        }
        sh[0][rg][ch] = s; sh[1][rg][ch] = s2;
        __syncthreads();
        if (rg == 0) {
            s  = sh[0][0][ch] + sh[0][1][ch] + sh[0][2][ch] + sh[0][3][ch];
            s2 = sh[1][0][ch] + sh[1][1][ch] + sh[1][2][ch] + sh[1][3][ch];
            atomicAdd(&g_st.sum[0][ch], s);
            atomicAdd(&g_st.sumsq[0][ch], s2);
        }
    }
    __threadfence();
    __syncthreads();
    if (threadIdx.x == 0) atomicAdd(&g_st.arrive, 1u);

    // weight conversion — hidden in the sync window
    const int wtotal = KK * CC * CC;
    for (int i = blockIdx.x * blockDim.x + threadIdx.x; i < wtotal;
         i += gridDim.x * blockDim.x) {
        int k  = i >> 12;
        int ci = (i & 4095) >> 6;
        int co = i & 63;
        uint32_t off = (uint32_t)SW(ci * 128 + co * 2) >> 1;
        g_Wh[0][k * 4096 + off] = __float2half_rn(W1[i]);
        g_Wh[1][k * 4096 + off] = __float2half_rn(W2[i]);
    }

    if (threadIdx.x == 0) {
        while (atomicAdd(&g_st.arrive, 0u) < (unsigned)gridDim.x) {}
    }
    __syncthreads();

    // phase B: finalize + BN + ReLU + fp16 quantize into g_y
    __shared__ float s_scale[CC], s_shift[CC];
    if (threadIdx.x < CC) {
        int c = threadIdx.x;
        float mean = g_st.sum[0][c] / (float)NV;
        float var  = g_st.sumsq[0][c] / (float)NV - mean * mean;
        float s = gamma1[c] * rsqrtf(var + BN_EPS);
        s_scale[c] = s;
        s_shift[c] = beta1[c] - mean * s;
    }
    __syncthreads();
    const int total = NV * CC / 8;
    for (int i = blockIdx.x * blockDim.x + threadIdx.x; i < total;
         i += gridDim.x * blockDim.x) {
        int cb = (i & 7) << 3;
        float4 u0 = ((const float4*)x)[2 * i];
        float4 u1 = ((const float4*)x)[2 * i + 1];
        float f[8] = {u0.x, u0.y, u0.z, u0.w, u1.x, u1.y, u1.z, u1.w};
        #pragma unroll
        for (int j = 0; j < 8; ++j)
            f[j] = fmaxf(fmaf(f[j], s_scale[cb + j], s_shift[cb + j]), 0.f);
        uint4 o;
        *(__half2*)&o.x = __floats2half2_rn(f[0], f[1]);
        *(__half2*)&o.y = __floats2half2_rn(f[2], f[3]);
        *(__half2*)&o.z = __floats2half2_rn(f[4], f[5]);
        *(__half2*)&o.w = __floats2half2_rn(f[6], f[7]);
        ((uint4*)g_y)[i] = o;
    }
}

// ---------------- bnrelu stage1: g_t16 -> BN2+ReLU -> g_y ----------------
__global__ void k_bnrelu1(const float* __restrict__ gamma,
                          const float* __restrict__ beta) {
    __shared__ float s_scale[CC], s_shift[CC];
    if (threadIdx.x < CC) {
        int c = threadIdx.x;
        float mean = g_st.sum[1][c] / (float)NV;
        float var  = g_st.sumsq[1][c] / (float)NV - mean * mean;
        float s = gamma[c] * rsqrtf(var + BN_EPS);
        s_scale[c] = s;
        s_shift[c] = beta[c] - mean * s;
    }
    __syncthreads();
    const int i = blockIdx.x * blockDim.x + threadIdx.x;
    if (i >= NV * CC / 8) return;
    int cb = (i & 7) << 3;
    uint4 u = ((const uint4*)g_t16)[i];
    float2 p0 = __half22float2(*(__half2*)&u.x);
    float2 p1 = __half22float2(*(__half2*)&u.y);
    float2 p2 = __half22float2(*(__half2*)&u.z);
    float2 p3 = __half22float2(*(__half2*)&u.w);
    float f[8] = {p0.x, p0.y, p1.x, p1.y, p2.x, p2.y, p3.x, p3.y};
    #pragma unroll
    for (int j = 0; j < 8; ++j)
        f[j] = fmaxf(fmaf(f[j], s_scale[cb + j], s_shift[cb + j]), 0.f);
    uint4 o;
    *(__half2*)&o.x = __floats2half2_rn(f[0], f[1]);
    *(__half2*)&o.y = __floats2half2_rn(f[2], f[3]);
    *(__half2*)&o.z = __floats2half2_rn(f[4], f[5]);
    *(__half2*)&o.w = __floats2half2_rn(f[6], f[7]);
    ((uint4*)g_y)[i] = o;
}

// ---------------- gather-GEMM conv: BM=128, 8 warps (4m x 2n, m32n32), occ 4 ----------------
__global__ void __launch_bounds__(NT, 4)
k_conv(const void* __restrict__ nbr, int which,
       const float* __restrict__ residual, float* __restrict__ dout)
{
    extern __shared__ char smem[];
    const uint32_t sb = smem_u32(smem);
    const __half* __restrict__ Wh = g_Wh[which];

    const int tid = threadIdx.x;
    const int warp = tid >> 5, lane = tid & 31;
    const int wm = warp >> 1, wn = warp & 1;
    const int m0 = blockIdx.x * BM;
    const bool is64 = (g_is64 != 0);

    float acc[2][4][4];
    #pragma unroll
    for (int a = 0; a < 2; ++a)
        #pragma unroll
        for (int b = 0; b < 4; ++b)
            #pragma unroll
            for (int c = 0; c < 4; ++c) acc[a][b][c] = 0.f;

    const int r  = tid >> 1;
    const int hs = tid & 1;
    const int gn = (m0 + r < NV) ? (m0 + r) : 0;

    auto fill = [&](int st, int gi, int k) {
        const __half* srcA = g_y + (size_t)gi * CC + hs * 32;
        uint32_t abase = sb + st * STAGE_BYTES;
        #pragma unroll
        for (int j = 0; j < 4; ++j) {
            uint32_t boff = (uint32_t)(r * 128 + (hs * 4 + j) * 16);
            cp16(abase + SW(boff), srcA + j * 8);
        }
        const __half* srcB = Wh + k * 4096;
        uint32_t bbase = abase + A_BYTES;
        cp16(bbase + tid * 16,        srcB + tid * 8);
        cp16(bbase + (tid + NT) * 16, srcB + (tid + NT) * 8);
    };

    {
        int i0 = ld_idx(nbr, is64, gn, 0);
        int i1 = ld_idx(nbr, is64, gn, 1);
        fill(0, i0, 0);
        asm volatile("cp.async.commit_group;\n");
        fill(1, i1, 1);
        asm volatile("cp.async.commit_group;\n");
    }
    int gi_next = ld_idx(nbr, is64, gn, 2);

    for (int k = 0; k < KK; ++k) {
        const int st = k & 1;
        if (k + 1 < KK)
            asm volatile("cp.async.wait_group 1;\n");
        else
            asm volatile("cp.async.wait_group 0;\n");
        __syncthreads();

        const uint32_t abase = sb + st * STAGE_BYTES;
        const uint32_t bbase = abase + A_BYTES;

        #pragma unroll
        for (int ks = 0; ks < 4; ++ks) {
            const int k0 = ks * 16;
            uint32_t a0[4], a1[4], b0[4], b1[4];
            {
                int row = wm * 32 + (lane & 15);
                int col = k0 + (lane >> 4) * 8;
                uint32_t ad = abase + SW((uint32_t)(row * 128 + col * 2));
                asm volatile("ldmatrix.sync.aligned.m8n8.x4.shared.b16 {%0,%1,%2,%3}, [%4];"
                             : "=r"(a0[0]), "=r"(a0[1]), "=r"(a0[2]), "=r"(a0[3]) : "r"(ad));
                ad = abase + SW((uint32_t)((row + 16) * 128 + col * 2));
                asm volatile("ldmatrix.sync.aligned.m8n8.x4.shared.b16 {%0,%1,%2,%3}, [%4];"
                             : "=r"(a1[0]), "=r"(a1[1]), "=r"(a1[2]), "=r"(a1[3]) : "r"(ad));
            }
            {
                int krow = k0 + ((lane >> 3) & 1) * 8 + (lane & 7);
                int coll = wn * 32 + (lane >> 4) * 8;
                uint32_t ad = bbase + SW((uint32_t)(krow * 128 + coll * 2));
                asm volatile("ldmatrix.sync.aligned.m8n8.x4.trans.shared.b16 {%0,%1,%2,%3}, [%4];"
                             : "=r"(b0[0]), "=r"(b0[1]), "=r"(b0[2]), "=r"(b0[3]) : "r"(ad));
                ad = bbase + SW((uint32_t)(krow * 128 + (coll + 16) * 2));
                asm volatile("ldmatrix.sync.aligned.m8n8.x4.trans.shared.b16 {%0,%1,%2,%3}, [%4];"
                             : "=r"(b1[0]), "=r"(b1[1]), "=r"(b1[2]), "=r"(b1[3]) : "r"(ad));
            }
            #pragma unroll
            for (int mt = 0; mt < 2; ++mt) {
                const uint32_t* A = mt ? a1 : a0;
                #pragma unroll
                for (int nt = 0; nt < 4; ++nt) {
                    const uint32_t* B = (nt < 2) ? b0 : b1;
                    uint32_t bb0 = B[(nt & 1) * 2], bb1 = B[(nt & 1) * 2 + 1];
                    float* C = acc[mt][nt];
                    asm volatile(
                        "mma.sync.aligned.m16n8k16.row.col.f32.f16.f16.f32 "
                        "{%0,%1,%2,%3}, {%4,%5,%6,%7}, {%8,%9}, {%0,%1,%2,%3};"
                        : "+f"(C[0]), "+f"(C[1]), "+f"(C[2]), "+f"(C[3])
                        : "r"(A[0]), "r"(A[1]), "r"(A[2]), "r"(A[3]),
                          "r"(bb0), "r"(bb1));
                }
            }
        }

        if (k + 2 < KK) {
            __syncthreads();
            fill(st, gi_next, k + 2);
            asm volatile("cp.async.commit_group;\n");
            gi_next = ld_idx(nbr, is64, gn, (k + 3 < KK) ? (k + 3) : (KK - 1));
        }
    }

    // ---- epilogue ----
    if (which == 0) {
        float ls[8], lq[8];
        #pragma unroll
        for (int j = 0; j < 8; ++j) { ls[j] = 0.f; lq[j] = 0.f; }

        #pragma unroll
        for (int mt = 0; mt < 2; ++mt) {
            int rbase = m0 + wm * 32 + mt * 16 + (lane >> 2);
            bool v0 = rbase < NV, v1 = rbase + 8 < NV;
            #pragma unroll
            for (int nt = 0; nt < 4; ++nt) {
                int col = wn * 32 + nt * 8 + (lane & 3) * 2;
                float* C = acc[mt][nt];
                if (v0) {
                    size_t o = (size_t)rbase * CC + col;
                    *(__half2*)(g_t16 + o) = __floats2half2_rn(C[0], C[1]);
                    ls[nt * 2]     += C[0]; lq[nt * 2]     += C[0] * C[0];
                    ls[nt * 2 + 1] += C[1]; lq[nt * 2 + 1] += C[1] * C[1];
                }
                if (v1) {
                    size_t o = (size_t)(rbase + 8) * CC + col;
                    *(__half2*)(g_t16 + o) = __floats2half2_rn(C[2], C[3]);
                    ls[nt * 2]     += C[2]; lq[nt * 2]     += C[2] * C[2];
                    ls[nt * 2 + 1] += C[3]; lq[nt * 2 + 1] += C[3] * C[3];
                }
            }
        }
        #pragma unroll
        for (int m = 4; m <= 16; m <<= 1) {
            #pragma unroll
            for (int j = 0; j < 8; ++j) {
                ls[j] += __shfl_xor_sync(0xffffffffu, ls[j], m);
                lq[j] += __shfl_xor_sync(0xffffffffu, lq[j], m);
            }
        }
        float* red = (float*)smem;
        __syncthreads();
        if ((lane >> 2) == 0) {
            #pragma unroll
            for (int j = 0; j < 8; ++j) {
                int cl = (j >> 1) * 8 + (lane & 3) * 2 + (j & 1);
                red[warp * 32 + cl]              = ls[j];
                red[NWARP * 32 + warp * 32 + cl] = lq[j];
            }
        }
        __syncthreads();
        if (tid < 128) {
            int part = tid >> 6, c = tid & 63;
            int cwn = c >> 5, cl = c & 31;
            const float* base = red + part * NWARP * 32;
            float v = 0.f;
            #pragma unroll
            for (int i = 0; i < 4; ++i) v += base[(2 * i + cwn) * 32 + cl];
            atomicAdd(part ? &g_st.sumsq[1][c] : &g_st.sum[1][c], v);
        }
    } else {
        #pragma unroll
        for (int mt = 0; mt < 2; ++mt) {
            int rbase = m0 + wm * 32 + mt * 16 + (lane >> 2);
            #pragma unroll
            for (int nt = 0; nt < 4; ++nt) {
                int col = wn * 32 + nt * 8 + (lane & 3) * 2;
                float* C = acc[mt][nt];
                if (rbase < NV) {
                    size_t o = (size_t)rbase * CC + col;
                    float2 rv = *(const float2*)(residual + o);
                    float2 v; v.x = C[0] + rv.x; v.y = C[1] + rv.y;
                    *(float2*)(dout + o) = v;
                }
                if (rbase + 8 < NV) {
                    size_t o = (size_t)(rbase + 8) * CC + col;
                    float2 rv = *(const float2*)(residual + o);
                    float2 v; v.x = C[2] + rv.x; v.y = C[3] + rv.y;
                    *(float2*)(dout + o) = v;
                }
            }
        }
    }
}

// ---------------- launch ----------------
extern "C" void kernel_launch(void* const* d_in, const int* in_sizes, int n_in,
                              void* d_out, int out_size) {
    const float* x      = (const float*)d_in[0];
    const void*  nbr    = d_in[1];
    const float* W1     = (const float*)d_in[2];
    const float* gamma1 = (const float*)d_in[3];
    const float* beta1  = (const float*)d_in[4];
    const float* W2     = (const float*)d_in[5];
    const float* gamma2 = (const float*)d_in[6];
    const float* beta2  = (const float*)d_in[7];
    float* out = (float*)d_out;

    const int conv_grid = (NV + BM - 1) / BM;          // 1563
    const int bn1_grid  = (NV * CC / 8 + 255) / 256;   // 6250

    static void* stats_addr = nullptr;
    if (!stats_addr) {
        cudaFuncSetAttribute(k_conv, cudaFuncAttributeMaxDynamicSharedMemorySize,
                             SMEM_CONV);
        cudaGetSymbolAddress(&stats_addr, g_st);
    }

    cudaMemsetAsync(stats_addr, 0, sizeof(Stats));                  // replaces k_zero
    k_prep<<<PREP_GRID, 256>>>(x, W1, W2, gamma1, beta1, nbr);      // 2
    k_conv<<<conv_grid, NT, SMEM_CONV>>>(nbr, 0, nullptr, nullptr); // 3
    k_bnrelu1<<<bn1_grid, 256>>>(gamma2, beta2);                    // 4 <- ncu
    k_conv<<<conv_grid, NT, SMEM_CONV>>>(nbr, 1, x, out);           // 5
}

// round 17
// speedup vs baseline: 1.0777x; 1.0022x over previous
#include <cuda_runtime.h>
#include <cuda_fp16.h>
#include <cstdint>

#define NV 200000
#define KK 27
#define CC 64
#define BM 128
#define NT 256
#define NWARP 8
#define STAGES 2
#define BN_EPS 1e-5f
#define PREP_GRID 740

#define A_BYTES (BM * 128)
#define B_BYTES (CC * 128)
#define STAGE_BYTES (A_BYTES + B_BYTES)            // 24576
#define SMEM_CONV (STAGES * STAGE_BYTES)           // 49152 -> 4 CTAs/SM

#define SW(o) ((o) ^ (((o) >> 3) & 0x70))

// ---------------- device scratch ----------------
__device__ alignas(256) __half g_y[(size_t)NV * CC];
__device__ alignas(256) __half g_t16[(size_t)NV * CC];
__device__ alignas(256) __half g_Wh[2][KK * CC * CC];

// zero-initialized at load; replay-invariant self-zeroing thereafter:
//   prep block0 zeros stage-1 stats (before conv1 writes them)
//   bnrelu1 block0 zeros stage-0 stats + arrive (for the next replay)
__device__ float g_sum[2][CC];
__device__ float g_sumsq[2][CC];
__device__ unsigned g_arrive;
__device__ int g_is64;

// ---------------- helpers ----------------
__device__ __forceinline__ uint32_t smem_u32(const void* p) {
    return (uint32_t)__cvta_generic_to_shared(p);
}
__device__ __forceinline__ void cp16(uint32_t dst, const void* src) {
    asm volatile("cp.async.cg.shared.global [%0], [%1], 16;\n" :: "r"(dst), "l"(src));
}
__device__ __forceinline__ int ld_idx(const void* nbr, bool is64, int gn, int k) {
    size_t pos = (size_t)gn * KK + k;
    return is64 ? (int)((const long long*)nbr)[pos] : ((const int*)nbr)[pos];
}

// ---------------- stats0 (MLP4) -> arrive -> wcvt (hidden) -> spin -> bnrelu0 ----------------
__global__ void __launch_bounds__(256, 5)
k_prep(const float* __restrict__ x,
       const float* __restrict__ W1,
       const float* __restrict__ W2,
       const float* __restrict__ gamma1,
       const float* __restrict__ beta1,
       const void* __restrict__ nbr) {
    // block 0: zero stage-1 stats for this replay + detect index dtype
    if (blockIdx.x == 0) {
        if (threadIdx.x < CC) {
            g_sum[1][threadIdx.x] = 0.f;
            g_sumsq[1][threadIdx.x] = 0.f;
        }
        if (threadIdx.x == 0) {
            const long long* p = (const long long*)nbr;
            int ok = 1;
            for (int i = 0; i < 64; ++i) {
                long long v = p[i];
                if (v < 0 || v >= NV) { ok = 0; break; }
            }
            g_is64 = ok;
        }
    }

    // phase A: column stats over x, 4 independent loads in flight
    __shared__ float sh[2][4][CC];
    {
        int ch = threadIdx.x & 63;
        int rg = threadIdx.x >> 6;
        const int G = gridDim.x * 4;
        float s = 0.f, s2 = 0.f;
        int row = blockIdx.x * 4 + rg;
        for (; row + 3 * G < NV; row += 4 * G) {
            float v0 = x[(size_t)row * CC + ch];
            float v1 = x[(size_t)(row + G) * CC + ch];
            float v2 = x[(size_t)(row + 2 * G) * CC + ch];
            float v3 = x[(size_t)(row + 3 * G) * CC + ch];
            s  += (v0 + v1) + (v2 + v3);
            s2 += ((v0 * v0 + v1 * v1) + (v2 * v2 + v3 * v3));
        }
        for (; row < NV; row += G) {
            float v = x[(size_t)row * CC + ch];
            s += v; s2 += v * v;
        }
        sh[0][rg][ch] = s; sh[1][rg][ch] = s2;
        __syncthreads();
        if (rg == 0) {
            s  = sh[0][0][ch] + sh[0][1][ch] + sh[0][2][ch] + sh[0][3][ch];
            s2 = sh[1][0][ch] + sh[1][1][ch] + sh[1][2][ch] + sh[1][3][ch];
            atomicAdd(&g_sum[0][ch], s);
            atomicAdd(&g_sumsq[0][ch], s2);
        }
    }
    __threadfence();
    __syncthreads();
    if (threadIdx.x == 0) atomicAdd(&g_arrive, 1u);

    // weight conversion — hidden in the sync window
    const int wtotal = KK * CC * CC;
    for (int i = blockIdx.x * blockDim.x + threadIdx.x; i < wtotal;
         i += gridDim.x * blockDim.x) {
        int k  = i >> 12;
        int ci = (i & 4095) >> 6;
        int co = i & 63;
        uint32_t off = (uint32_t)SW(ci * 128 + co * 2) >> 1;
        g_Wh[0][k * 4096 + off] = __float2half_rn(W1[i]);
        g_Wh[1][k * 4096 + off] = __float2half_rn(W2[i]);
    }

    if (threadIdx.x == 0) {
        while (atomicAdd(&g_arrive, 0u) < (unsigned)gridDim.x) {}
    }
    __syncthreads();

    // phase B: finalize + BN + ReLU + fp16 quantize into g_y
    __shared__ float s_scale[CC], s_shift[CC];
    if (threadIdx.x < CC) {
        int c = threadIdx.x;
        float mean = g_sum[0][c] / (float)NV;
        float var  = g_sumsq[0][c] / (float)NV - mean * mean;
        float s = gamma1[c] * rsqrtf(var + BN_EPS);
        s_scale[c] = s;
        s_shift[c] = beta1[c] - mean * s;
    }
    __syncthreads();
    const int total = NV * CC / 8;
    for (int i = blockIdx.x * blockDim.x + threadIdx.x; i < total;
         i += gridDim.x * blockDim.x) {
        int cb = (i & 7) << 3;
        float4 u0 = ((const float4*)x)[2 * i];
        float4 u1 = ((const float4*)x)[2 * i + 1];
        float f[8] = {u0.x, u0.y, u0.z, u0.w, u1.x, u1.y, u1.z, u1.w};
        #pragma unroll
        for (int j = 0; j < 8; ++j)
            f[j] = fmaxf(fmaf(f[j], s_scale[cb + j], s_shift[cb + j]), 0.f);
        uint4 o;
        *(__half2*)&o.x = __floats2half2_rn(f[0], f[1]);
        *(__half2*)&o.y = __floats2half2_rn(f[2], f[3]);
        *(__half2*)&o.z = __floats2half2_rn(f[4], f[5]);
        *(__half2*)&o.w = __floats2half2_rn(f[6], f[7]);
        ((uint4*)g_y)[i] = o;
    }
}

// ---------------- bnrelu stage1: g_t16 -> BN2+ReLU -> g_y, 2 uint4/thread ----------------
__global__ void k_bnrelu1(const float* __restrict__ gamma,
                          const float* __restrict__ beta) {
    // reset prep-internal state for the next replay
    if (blockIdx.x == 0) {
        if (threadIdx.x < CC) {
            g_sum[0][threadIdx.x] = 0.f;
            g_sumsq[0][threadIdx.x] = 0.f;
        }
        if (threadIdx.x == 0) g_arrive = 0u;
    }
    __shared__ float s_scale[CC], s_shift[CC];
    if (threadIdx.x < CC) {
        int c = threadIdx.x;
        float mean = g_sum[1][c] / (float)NV;
        float var  = g_sumsq[1][c] / (float)NV - mean * mean;
        float s = gamma[c] * rsqrtf(var + BN_EPS);
        s_scale[c] = s;
        s_shift[c] = beta[c] - mean * s;
    }
    __syncthreads();
    const int total = NV * CC / 8;
    const int i0 = (blockIdx.x * blockDim.x + threadIdx.x) * 2;
    if (i0 >= total) return;
    // two independent loads in flight
    uint4 u0 = ((const uint4*)g_t16)[i0];
    uint4 u1 = (i0 + 1 < total) ? ((const uint4*)g_t16)[i0 + 1] : make_uint4(0, 0, 0, 0);
    #pragma unroll
    for (int e = 0; e < 2; ++e) {
        int i = i0 + e;
        if (i >= total) break;
        uint4 u = e ? u1 : u0;
        int cb = (i & 7) << 3;
        float2 p0 = __half22float2(*(__half2*)&u.x);
        float2 p1 = __half22float2(*(__half2*)&u.y);
        float2 p2 = __half22float2(*(__half2*)&u.z);
        float2 p3 = __half22float2(*(__half2*)&u.w);
        float f[8] = {p0.x, p0.y, p1.x, p1.y, p2.x, p2.y, p3.x, p3.y};
        #pragma unroll
        for (int j = 0; j < 8; ++j)
            f[j] = fmaxf(fmaf(f[j], s_scale[cb + j], s_shift[cb + j]), 0.f);
        uint4 o;
        *(__half2*)&o.x = __floats2half2_rn(f[0], f[1]);
        *(__half2*)&o.y = __floats2half2_rn(f[2], f[3]);
        *(__half2*)&o.z = __floats2half2_rn(f[4], f[5]);
        *(__half2*)&o.w = __floats2half2_rn(f[6], f[7]);
        ((uint4*)g_y)[i] = o;
    }
}

// ---------------- gather-GEMM conv: BM=128, 8 warps (4m x 2n, m32n32), occ 4 ----------------
__global__ void __launch_bounds__(NT, 4)
k_conv(const void* __restrict__ nbr, int which,
       const float* __restrict__ residual, float* __restrict__ dout)
{
    extern __shared__ char smem[];
    const uint32_t sb = smem_u32(smem);
    const __half* __restrict__ Wh = g_Wh[which];

    const int tid = threadIdx.x;
    const int warp = tid >> 5, lane = tid & 31;
    const int wm = warp >> 1, wn = warp & 1;
    const int m0 = blockIdx.x * BM;
    const bool is64 = (g_is64 != 0);

    float acc[2][4][4];
    #pragma unroll
    for (int a = 0; a < 2; ++a)
        #pragma unroll
        for (int b = 0; b < 4; ++b)
            #pragma unroll
            for (int c = 0; c < 4; ++c) acc[a][b][c] = 0.f;

    const int r  = tid >> 1;
    const int hs = tid & 1;
    const int gn = (m0 + r < NV) ? (m0 + r) : 0;

    auto fill = [&](int st, int gi, int k) {
        const __half* srcA = g_y + (size_t)gi * CC + hs * 32;
        uint32_t abase = sb + st * STAGE_BYTES;
        #pragma unroll
        for (int j = 0; j < 4; ++j) {
            uint32_t boff = (uint32_t)(r * 128 + (hs * 4 + j) * 16);
            cp16(abase + SW(boff), srcA + j * 8);
        }
        const __half* srcB = Wh + k * 4096;
        uint32_t bbase = abase + A_BYTES;
        cp16(bbase + tid * 16,        srcB + tid * 8);
        cp16(bbase + (tid + NT) * 16, srcB + (tid + NT) * 8);
    };

    {
        int i0 = ld_idx(nbr, is64, gn, 0);
        int i1 = ld_idx(nbr, is64, gn, 1);
        fill(0, i0, 0);
        asm volatile("cp.async.commit_group;\n");
        fill(1, i1, 1);
        asm volatile("cp.async.commit_group;\n");
    }
    int gi_next = ld_idx(nbr, is64, gn, 2);

    for (int k = 0; k < KK; ++k) {
        const int st = k & 1;
        if (k + 1 < KK)
            asm volatile("cp.async.wait_group 1;\n");
        else
            asm volatile("cp.async.wait_group 0;\n");
        __syncthreads();

        const uint32_t abase = sb + st * STAGE_BYTES;
        const uint32_t bbase = abase + A_BYTES;

        #pragma unroll
        for (int ks = 0; ks < 4; ++ks) {
            const int k0 = ks * 16;
            uint32_t a0[4], a1[4], b0[4], b1[4];
            {
                int row = wm * 32 + (lane & 15);
                int col = k0 + (lane >> 4) * 8;
                uint32_t ad = abase + SW((uint32_t)(row * 128 + col * 2));
                asm volatile("ldmatrix.sync.aligned.m8n8.x4.shared.b16 {%0,%1,%2,%3}, [%4];"
                             : "=r"(a0[0]), "=r"(a0[1]), "=r"(a0[2]), "=r"(a0[3]) : "r"(ad));
                ad = abase + SW((uint32_t)((row + 16) * 128 + col * 2));
                asm volatile("ldmatrix.sync.aligned.m8n8.x4.shared.b16 {%0,%1,%2,%3}, [%4];"
                             : "=r"(a1[0]), "=r"(a1[1]), "=r"(a1[2]), "=r"(a1[3]) : "r"(ad));
            }
            {
                int krow = k0 + ((lane >> 3) & 1) * 8 + (lane & 7);
                int coll = wn * 32 + (lane >> 4) * 8;
                uint32_t ad = bbase + SW((uint32_t)(krow * 128 + coll * 2));
                asm volatile("ldmatrix.sync.aligned.m8n8.x4.trans.shared.b16 {%0,%1,%2,%3}, [%4];"
                             : "=r"(b0[0]), "=r"(b0[1]), "=r"(b0[2]), "=r"(b0[3]) : "r"(ad));
                ad = bbase + SW((uint32_t)(krow * 128 + (coll + 16) * 2));
                asm volatile("ldmatrix.sync.aligned.m8n8.x4.trans.shared.b16 {%0,%1,%2,%3}, [%4];"
                             : "=r"(b1[0]), "=r"(b1[1]), "=r"(b1[2]), "=r"(b1[3]) : "r"(ad));
            }
            #pragma unroll
            for (int mt = 0; mt < 2; ++mt) {
                const uint32_t* A = mt ? a1 : a0;
                #pragma unroll
                for (int nt = 0; nt < 4; ++nt) {
                    const uint32_t* B = (nt < 2) ? b0 : b1;
                    uint32_t bb0 = B[(nt & 1) * 2], bb1 = B[(nt & 1) * 2 + 1];
                    float* C = acc[mt][nt];
                    asm volatile(
                        "mma.sync.aligned.m16n8k16.row.col.f32.f16.f16.f32 "
                        "{%0,%1,%2,%3}, {%4,%5,%6,%7}, {%8,%9}, {%0,%1,%2,%3};"
                        : "+f"(C[0]), "+f"(C[1]), "+f"(C[2]), "+f"(C[3])
                        : "r"(A[0]), "r"(A[1]), "r"(A[2]), "r"(A[3]),
                          "r"(bb0), "r"(bb1));
                }
            }
        }

        if (k + 2 < KK) {
            __syncthreads();
            fill(st, gi_next, k + 2);
            asm volatile("cp.async.commit_group;\n");
            gi_next = ld_idx(nbr, is64, gn, (k + 3 < KK) ? (k + 3) : (KK - 1));
        }
    }

    // ---- epilogue ----
    if (which == 0) {
        float ls[8], lq[8];
        #pragma unroll
        for (int j = 0; j < 8; ++j) { ls[j] = 0.f; lq[j] = 0.f; }

        #pragma unroll
        for (int mt = 0; mt < 2; ++mt) {
            int rbase = m0 + wm * 32 + mt * 16 + (lane >> 2);
            bool v0 = rbase < NV, v1 = rbase + 8 < NV;
            #pragma unroll
            for (int nt = 0; nt < 4; ++nt) {
                int col = wn * 32 + nt * 8 + (lane & 3) * 2;
                float* C = acc[mt][nt];
                if (v0) {
                    size_t o = (size_t)rbase * CC + col;
                    *(__half2*)(g_t16 + o) = __floats2half2_rn(C[0], C[1]);
                    ls[nt * 2]     += C[0]; lq[nt * 2]     += C[0] * C[0];
                    ls[nt * 2 + 1] += C[1]; lq[nt * 2 + 1] += C[1] * C[1];
                }
                if (v1) {
                    size_t o = (size_t)(rbase + 8) * CC + col;
                    *(__half2*)(g_t16 + o) = __floats2half2_rn(C[2], C[3]);
                    ls[nt * 2]     += C[2]; lq[nt * 2]     += C[2] * C[2];
                    ls[nt * 2 + 1] += C[3]; lq[nt * 2 + 1] += C[3] * C[3];
                }
            }
        }
        #pragma unroll
        for (int m = 4; m <= 16; m <<= 1) {
            #pragma unroll
            for (int j = 0; j < 8; ++j) {
                ls[j] += __shfl_xor_sync(0xffffffffu, ls[j], m);
                lq[j] += __shfl_xor_sync(0xffffffffu, lq[j], m);
            }
        }
        float* red = (float*)smem;
        __syncthreads();
        if ((lane >> 2) == 0) {
            #pragma unroll
            for (int j = 0; j < 8; ++j) {
                int cl = (j >> 1) * 8 + (lane & 3) * 2 + (j & 1);
                red[warp * 32 + cl]              = ls[j];
                red[NWARP * 32 + warp * 32 + cl] = lq[j];
            }
        }
        __syncthreads();
        if (tid < 128) {
            int part = tid >> 6, c = tid & 63;
            int cwn = c >> 5, cl = c & 31;
            const float* base = red + part * NWARP * 32;
            float v = 0.f;
            #pragma unroll
            for (int i = 0; i < 4; ++i) v += base[(2 * i + cwn) * 32 + cl];
            atomicAdd(part ? &g_sumsq[1][c] : &g_sum[1][c], v);
        }
    } else {
        #pragma unroll
        for (int mt = 0; mt < 2; ++mt) {
            int rbase = m0 + wm * 32 + mt * 16 + (lane >> 2);
            #pragma unroll
            for (int nt = 0; nt < 4; ++nt) {
                int col = wn * 32 + nt * 8 + (lane & 3) * 2;
                float* C = acc[mt][nt];
                if (rbase < NV) {
                    size_t o = (size_t)rbase * CC + col;
                    float2 rv = *(const float2*)(residual + o);
                    float2 v; v.x = C[0] + rv.x; v.y = C[1] + rv.y;
                    *(float2*)(dout + o) = v;
                }
                if (rbase + 8 < NV) {
                    size_t o = (size_t)(rbase + 8) * CC + col;
                    float2 rv = *(const float2*)(residual + o);
                    float2 v; v.x = C[2] + rv.x; v.y = C[3] + rv.y;
                    *(float2*)(dout + o) = v;
                }
            }
        }
    }
}

// ---------------- launch ----------------
extern "C" void kernel_launch(void* const* d_in, const int* in_sizes, int n_in,
                              void* d_out, int out_size) {
    const float* x      = (const float*)d_in[0];
    const void*  nbr    = d_in[1];
    const float* W1     = (const float*)d_in[2];
    const float* gamma1 = (const float*)d_in[3];
    const float* beta1  = (const float*)d_in[4];
    const float* W2     = (const float*)d_in[5];
    const float* gamma2 = (const float*)d_in[6];
    const float* beta2  = (const float*)d_in[7];
    float* out = (float*)d_out;

    const int conv_grid = (NV + BM - 1) / BM;              // 1563
    const int bn1_grid  = (NV * CC / 16 + 255) / 256;      // 3125 (2 uint4/thread)

    static int attr_set = 0;
    if (!attr_set) {
        cudaFuncSetAttribute(k_conv, cudaFuncAttributeMaxDynamicSharedMemorySize,
                             SMEM_CONV);
        attr_set = 1;
    }

    k_prep<<<PREP_GRID, 256>>>(x, W1, W2, gamma1, beta1, nbr);      // 1
    k_conv<<<conv_grid, NT, SMEM_CONV>>>(nbr, 0, nullptr, nullptr); // 2
    k_bnrelu1<<<bn1_grid, 256>>>(gamma2, beta2);                    // 3
    k_conv<<<conv_grid, NT, SMEM_CONV>>>(nbr, 1, x, out);           // 4
}